// round 4
// baseline (speedup 1.0000x reference)
#include <cuda_runtime.h>
#include <cuda_bf16.h>
#include <cub/cub.cuh>

// Problem-fixed sizes (setup_inputs): N=400000 verts, F=2000000 tets.
#define NVV 400000
#define NFF 2000000
#define MAXE (NFF * 4)            // max crossing-edge slots (<=4 per tet)
#define EDOM (NVV + MAXE)         // tet-vertex id domain for unique()
#define SENTK ((1ull << 38) - 1ull)
#define M21 0x1FFFFFll

// ---------------- constant tables ----------------
__constant__ int c_TRI[16][6] = {
    {-1,-1,-1,-1,-1,-1},{1,0,2,-1,-1,-1},{4,0,3,-1,-1,-1},{1,4,2,1,3,4},
    {3,1,5,-1,-1,-1},{2,3,0,2,5,3},{1,4,0,1,5,4},{4,2,5,-1,-1,-1},
    {4,5,2,-1,-1,-1},{4,1,0,4,5,1},{3,2,0,3,5,2},{1,3,5,-1,-1,-1},
    {4,1,2,4,3,1},{3,0,4,-1,-1,-1},{2,0,1,-1,-1,-1},{-1,-1,-1,-1,-1,-1}};
__constant__ int c_NT[16]  = {0,1,1,2,1,2,2,1,1,2,2,1,2,1,1,0};
// NUM_TETS with code 15 zeroed (inner tets handled separately)
__constant__ int c_NTT[16] = {0,1,1,3,1,3,3,3,1,3,3,3,3,3,3,0};
__constant__ int c_TET[16][12] = {
    {-1,-1,-1,-1,-1,-1,-1,-1,-1,-1,-1,-1},{0,4,5,6,-1,-1,-1,-1,-1,-1,-1,-1},
    {1,4,8,7,-1,-1,-1,-1,-1,-1,-1,-1},{7,1,8,6,5,1,7,6,5,0,1,6},
    {2,5,7,9,-1,-1,-1,-1,-1,-1,-1,-1},{4,0,6,7,9,0,7,6,7,0,9,2},
    {4,1,9,8,5,1,9,4,5,1,2,9},{6,0,1,2,8,6,1,2,9,6,8,2},
    {3,6,9,8,-1,-1,-1,-1,-1,-1,-1,-1},{5,0,4,8,5,0,8,3,5,8,9,3},
    {1,4,7,3,4,7,6,3,9,6,7,3},{0,1,5,3,5,1,9,3,5,1,7,9},
    {5,2,3,7,3,6,5,8,3,5,7,8},{0,4,7,8,0,3,8,7,0,3,7,2},
    {4,1,2,3,4,3,2,5,4,3,5,6},{0,1,2,3,-1,-1,-1,-1,-1,-1,-1,-1}};
__constant__ int c_E0[6] = {0,0,0,1,1,2};
__constant__ int c_E1[6] = {1,2,3,2,3,3};

// ---------------- device scratch (static, no runtime alloc) ----------------
__device__ unsigned char      g_occ[NVV];
__device__ unsigned char      g_code[NFF];
__device__ unsigned long long g_key[MAXE];
__device__ unsigned long long g_key_alt[MAXE];
__device__ unsigned int       g_pay[MAXE];
__device__ unsigned int       g_pay_alt[MAXE];
__device__ int                g_flag[MAXE];
__device__ int                g_fexcl[MAXE];
__device__ int                g_interp[2 * MAXE];
__device__ int                g_idxmap[NFF * 6];
__device__ unsigned long long g_packA[NFF], g_packB[NFF];
__device__ unsigned long long g_exclA[NFF], g_exclB[NFF];
__device__ int                g_present[EDOM];
__device__ int                g_rank[EDOM];
__device__ unsigned char      g_temp[256u << 20];   // CUB temp storage

struct Meta {
    int E;
    int c_nt1, c_nt2, c_ntt1, c_ntt3, c_inner;
    int U;
    long long off_faces, off_vtm, off_tets;
};
__device__ Meta g_meta;

// ---------------- kernels ----------------
__global__ void k_occ(const float* __restrict__ sdf, const float* __restrict__ thp, int n) {
    int i = blockIdx.x * blockDim.x + threadIdx.x;
    if (i >= n) return;
    float s = sdf[i], t = thp[0];
    g_occ[i] = (s > 0.f && s <= t) ? 1 : 0;
}

__global__ void k_tetproc(const int4* __restrict__ tet4, int F) {
    int t = blockIdx.x * blockDim.x + threadIdx.x;
    if (t >= F) return;
    int4 v = tet4[t];
    int o0 = g_occ[v.x], o1 = g_occ[v.y], o2 = g_occ[v.z], o3 = g_occ[v.w];
    int code = o0 | (o1 << 1) | (o2 << 2) | (o3 << 3);
    g_code[t] = (unsigned char)code;
    int nt = c_NT[code], ntt = c_NTT[code];
    g_packA[t] = (unsigned long long)(nt == 1)
               | ((unsigned long long)(nt == 2) << 21)
               | ((unsigned long long)(ntt == 1) << 42);
    g_packB[t] = (unsigned long long)(ntt == 3)
               | ((unsigned long long)(code == 15) << 21);

    unsigned long long keys[4] = {SENTK, SENTK, SENTK, SENTK};
    unsigned int pays[4] = {0, 0, 0, 0};
    if (code >= 1 && code <= 14) {
        int vv[4] = {v.x, v.y, v.z, v.w};
        int oo[4] = {o0, o1, o2, o3};
        int slot = 0;
        #pragma unroll
        for (int e = 0; e < 6; e++) {
            int ia = c_E0[e], ib = c_E1[e];
            if (oo[ia] + oo[ib] == 1) {
                int a = vv[ia], b = vv[ib];
                int lo = a < b ? a : b;
                int hi = a < b ? b : a;
                keys[slot] = ((unsigned long long)lo << 19) | (unsigned long long)hi;
                pays[slot] = (unsigned int)(t * 6 + e);
                slot++;
            }
        }
    }
    ((ulonglong2*)g_key)[2*t]     = make_ulonglong2(keys[0], keys[1]);
    ((ulonglong2*)g_key)[2*t + 1] = make_ulonglong2(keys[2], keys[3]);
    ((uint4*)g_pay)[t] = make_uint4(pays[0], pays[1], pays[2], pays[3]);
}

__global__ void k_flags(const unsigned long long* __restrict__ keys) {
    int i = blockIdx.x * blockDim.x + threadIdx.x;
    if (i >= MAXE) return;
    unsigned long long k = keys[i];
    g_flag[i] = (k != SENTK && (i == 0 || keys[i-1] != k)) ? 1 : 0;
}

__global__ void k_postsort(const unsigned long long* __restrict__ keys,
                           const unsigned int* __restrict__ pays) {
    int i = blockIdx.x * blockDim.x + threadIdx.x;
    if (i >= MAXE) return;
    unsigned long long k = keys[i];
    if (k != SENTK) {
        int u = g_fexcl[i] + g_flag[i] - 1;   // crossing-edge rank for this key
        g_idxmap[pays[i]] = u;
        if (g_flag[i]) {
            g_interp[2*u]     = (int)(k >> 19);
            g_interp[2*u + 1] = (int)(k & ((1u << 19) - 1));
        }
    }
    if (i == MAXE - 1) g_meta.E = g_fexcl[i] + g_flag[i];
}

__global__ void k_meta1(int F) {
    unsigned long long a = g_exclA[F-1] + g_packA[F-1];
    unsigned long long b = g_exclB[F-1] + g_packB[F-1];
    g_meta.c_nt1  = (int)(a & M21);
    g_meta.c_nt2  = (int)((a >> 21) & M21);
    g_meta.c_ntt1 = (int)((a >> 42) & M21);
    g_meta.c_ntt3 = (int)(b & M21);
    g_meta.c_inner = (int)((b >> 21) & M21);
    long long nf = (long long)g_meta.c_nt1 + 2ll * g_meta.c_nt2;
    g_meta.off_faces = 3ll * g_meta.E;
    g_meta.off_vtm   = g_meta.off_faces + 3ll * nf;
}

__global__ void k_verts(const float* __restrict__ pos, const float* __restrict__ sdf,
                        const float* __restrict__ thp, float* __restrict__ out) {
    int i = blockIdx.x * blockDim.x + threadIdx.x;
    if (i >= g_meta.E) return;
    int v0 = g_interp[2*i], v1 = g_interp[2*i + 1];
    float a = sdf[v0], b = sdf[v1];
    float th = thp[0];
    if (a > 0.f && b > 0.f) { a -= th; b -= th; }
    float denom = a - b;
    float w0 = -b / denom;
    float w1 =  a / denom;
    out[3*i + 0] = pos[3*v0 + 0] * w0 + pos[3*v1 + 0] * w1;
    out[3*i + 1] = pos[3*v0 + 1] * w0 + pos[3*v1 + 1] * w1;
    out[3*i + 2] = pos[3*v0 + 2] * w0 + pos[3*v1 + 2] * w1;
}

__global__ void k_faces(float* __restrict__ out, int F) {
    int t = blockIdx.x * blockDim.x + threadIdx.x;
    if (t >= F) return;
    int code = g_code[t];
    int nt = c_NT[code];
    if (nt == 0) return;
    if (nt == 1) {
        long long r = (long long)(g_exclA[t] & M21);
        long long base = g_meta.off_faces + 3ll * r;
        #pragma unroll
        for (int j = 0; j < 3; j++)
            out[base + j] = (float)g_idxmap[6*t + c_TRI[code][j]];
    } else {
        long long r = (long long)((g_exclA[t] >> 21) & M21);
        long long base = g_meta.off_faces + 3ll * ((long long)g_meta.c_nt1 + 2ll * r);
        #pragma unroll
        for (int j = 0; j < 6; j++)
            out[base + j] = (float)g_idxmap[6*t + c_TRI[code][j]];
    }
}

__global__ void k_mark(const int4* __restrict__ tet4, int F, int N) {
    int t = blockIdx.x * blockDim.x + threadIdx.x;
    if (t >= F) return;
    int code = g_code[t];
    if (code == 0) return;
    int4 v = tet4[t];
    int vv[4] = {v.x, v.y, v.z, v.w};
    if (code == 15) {
        #pragma unroll
        for (int c = 0; c < 4; c++) g_present[vv[c]] = 1;
        return;
    }
    int ntt = c_NTT[code];
    for (int r = 0; r < ntt; r++) {
        #pragma unroll
        for (int c = 0; c < 4; c++) {
            int tv = c_TET[code][4*r + c];
            int val = (tv < 4) ? vv[tv] : N + g_idxmap[6*t + (tv - 4)];
            g_present[val] = 1;
        }
    }
}

__global__ void k_meta2() {
    int U = g_rank[EDOM - 1] + g_present[EDOM - 1];
    g_meta.U = U;
    g_meta.off_tets = g_meta.off_vtm + 3ll * U;
}

__global__ void k_vtm(const float* __restrict__ pos, float* __restrict__ out, int N) {
    int v = blockIdx.x * blockDim.x + threadIdx.x;
    if (v >= EDOM) return;
    if (!g_present[v]) return;
    long long r = g_rank[v];
    long long o = g_meta.off_vtm + 3ll * r;
    if (v < N) {
        out[o + 0] = pos[3*v + 0];
        out[o + 1] = pos[3*v + 1];
        out[o + 2] = pos[3*v + 2];
    } else {
        int e = v - N;   // verts live at the front of d_out
        out[o + 0] = out[3*e + 0];
        out[o + 1] = out[3*e + 1];
        out[o + 2] = out[3*e + 2];
    }
}

__global__ void k_tetout(const int4* __restrict__ tet4, float* __restrict__ out, int F, int N) {
    int t = blockIdx.x * blockDim.x + threadIdx.x;
    if (t >= F) return;
    int code = g_code[t];
    if (code == 0) return;
    int4 v = tet4[t];
    int vv[4] = {v.x, v.y, v.z, v.w};
    if (code == 15) {
        long long row = (long long)g_meta.c_ntt1 + 3ll * g_meta.c_ntt3
                      + (long long)((g_exclB[t] >> 21) & M21);
        long long base = g_meta.off_tets + 4ll * row;
        #pragma unroll
        for (int c = 0; c < 4; c++)
            out[base + c] = (float)g_rank[vv[c]];
        return;
    }
    int ntt = c_NTT[code];
    long long row0 = (ntt == 1)
        ? (long long)((g_exclA[t] >> 42) & M21)
        : (long long)g_meta.c_ntt1 + 3ll * (long long)(g_exclB[t] & M21);
    for (int r = 0; r < ntt; r++) {
        long long base = g_meta.off_tets + 4ll * (row0 + r);
        #pragma unroll
        for (int c = 0; c < 4; c++) {
            int tv = c_TET[code][4*r + c];
            int val = (tv < 4) ? vv[tv] : N + g_idxmap[6*t + (tv - 4)];
            out[base + c] = (float)g_rank[val];
        }
    }
}

// ---------------- host launch ----------------
extern "C" void kernel_launch(void* const* d_in, const int* in_sizes, int n_in,
                              void* d_out, int out_size) {
    const float* pos = (const float*)d_in[0];
    const float* sdf = (const float*)d_in[1];
    const int4*  tet = (const int4*)d_in[2];
    const float* th  = (const float*)d_in[3];
    float* out = (float*)d_out;
    int N = in_sizes[1];
    int F = in_sizes[2] / 4;
    const int B = 256;
    (void)n_in; (void)out_size;

    void *pk, *pka, *pp, *ppa, *ptmp, *pflag, *pfex, *ppA, *peA, *ppB, *peB, *ppres, *prank;
    cudaGetSymbolAddress(&pk,    g_key);
    cudaGetSymbolAddress(&pka,   g_key_alt);
    cudaGetSymbolAddress(&pp,    g_pay);
    cudaGetSymbolAddress(&ppa,   g_pay_alt);
    cudaGetSymbolAddress(&ptmp,  g_temp);
    cudaGetSymbolAddress(&pflag, g_flag);
    cudaGetSymbolAddress(&pfex,  g_fexcl);
    cudaGetSymbolAddress(&ppA,   g_packA);
    cudaGetSymbolAddress(&peA,   g_exclA);
    cudaGetSymbolAddress(&ppB,   g_packB);
    cudaGetSymbolAddress(&peB,   g_exclB);
    cudaGetSymbolAddress(&ppres, g_present);
    cudaGetSymbolAddress(&prank, g_rank);

    k_occ<<<(N + B - 1) / B, B>>>(sdf, th, N);
    k_tetproc<<<(F + B - 1) / B, B>>>(tet, F);

    // Sort crossing-edge keys (38-bit) with payloads
    cub::DoubleBuffer<unsigned long long> dk((unsigned long long*)pk, (unsigned long long*)pka);
    cub::DoubleBuffer<unsigned int>       dv((unsigned int*)pp, (unsigned int*)ppa);
    size_t tb = 0;
    cub::DeviceRadixSort::SortPairs(nullptr, tb, dk, dv, MAXE, 0, 38);
    cub::DeviceRadixSort::SortPairs(ptmp, tb, dk, dv, MAXE, 0, 38);
    const unsigned long long* skeys = dk.Current();
    const unsigned int*       spays = dv.Current();

    k_flags<<<(MAXE + B - 1) / B, B>>>(skeys);

    tb = 0;
    cub::DeviceScan::ExclusiveSum(nullptr, tb, (int*)pflag, (int*)pfex, MAXE);
    cub::DeviceScan::ExclusiveSum(ptmp, tb, (int*)pflag, (int*)pfex, MAXE);

    k_postsort<<<(MAXE + B - 1) / B, B>>>(skeys, spays);

    tb = 0;
    cub::DeviceScan::ExclusiveSum(nullptr, tb, (unsigned long long*)ppA, (unsigned long long*)peA, F);
    cub::DeviceScan::ExclusiveSum(ptmp, tb, (unsigned long long*)ppA, (unsigned long long*)peA, F);
    tb = 0;
    cub::DeviceScan::ExclusiveSum(nullptr, tb, (unsigned long long*)ppB, (unsigned long long*)peB, F);
    cub::DeviceScan::ExclusiveSum(ptmp, tb, (unsigned long long*)ppB, (unsigned long long*)peB, F);

    k_meta1<<<1, 1>>>(F);
    k_verts<<<(MAXE + B - 1) / B, B>>>(pos, sdf, th, out);
    k_faces<<<(F + B - 1) / B, B>>>(out, F);

    cudaMemsetAsync(ppres, 0, sizeof(int) * (size_t)EDOM);
    k_mark<<<(F + B - 1) / B, B>>>(tet, F, N);

    tb = 0;
    cub::DeviceScan::ExclusiveSum(nullptr, tb, (int*)ppres, (int*)prank, EDOM);
    cub::DeviceScan::ExclusiveSum(ptmp, tb, (int*)ppres, (int*)prank, EDOM);

    k_meta2<<<1, 1>>>();
    k_vtm<<<(EDOM + B - 1) / B, B>>>(pos, out, N);
    k_tetout<<<(F + B - 1) / B, B>>>(tet, out, F, N);
}